// round 2
// baseline (speedup 1.0000x reference)
#include <cuda_runtime.h>

// ---------------------------------------------------------------------------
// Output = [B=128, T=512, 66]; all B rows identical (decoder ignores encoder,
// zero init state, constant first input emb[0]). fc folds into the recurrence:
//   g_{t+1} = Wc @ h_t + b_comb,  Wc = dec_W_ih @ fc_W + dec_W_hh  (264 x 66)
//   g_1     = dec_W_ih @ emb[0] + (dec_b_ih + dec_b_hh)
// Rows of Wc are PERMUTED so that gates (i,f,g,o) of unit u sit at rows
// 4u..4u+3 -> adjacent lanes of one warp -> gate combine via shfl, 1 barrier.
// ---------------------------------------------------------------------------

#define DEC_H 66
#define G4    264        // 4 * DEC_H
#define EMBED 128
#define HPAD  68         // DEC_H padded to multiple of 4
#define MAXT  1024

__device__ __align__(16) float g_Wc[G4 * HPAD];      // permuted rows, padded
__device__ float g_bias[G4];                          // permuted
__device__ float g_gx0[G4];                           // permuted
__device__ __align__(16) float g_hist[MAXT * DEC_H];  // h trajectory [T,66]

typedef unsigned long long ull;

__device__ __forceinline__ void fma2(ull& acc, ull a, ull b) {
    asm("fma.rn.f32x2 %0, %1, %2, %0;" : "+l"(acc) : "l"(a), "l"(b));
}
__device__ __forceinline__ void add2(ull& a, ull b) {
    asm("add.rn.f32x2 %0, %0, %1;" : "+l"(a) : "l"(b));
}
__device__ __forceinline__ float2 up2(ull v) {
    float2 r;
    asm("mov.b64 {%0, %1}, %2;" : "=f"(r.x), "=f"(r.y) : "l"(v));
    return r;
}

__device__ __forceinline__ float fast_sigmoid(float x) {
    float e;
    asm("ex2.approx.f32 %0, %1;" : "=f"(e) : "f"(-1.4426950408889634f * x));
    float r;
    asm("rcp.approx.f32 %0, %1;" : "=f"(r) : "f"(1.0f + e));
    return r;
}
__device__ __forceinline__ float fast_tanh(float x) {
    x = fminf(20.0f, fmaxf(-20.0f, x));
    float e;
    asm("ex2.approx.f32 %0, %1;" : "=f"(e) : "f"(2.885390081777927f * x));
    float r;
    asm("rcp.approx.f32 %0, %1;" : "=f"(r) : "f"(e + 1.0f));
    return (e - 1.0f) * r;
}

// ---------------------------------------------------------------------------
// Kernel 1: fold fc; permute rows; 4 accumulators to break the serial chain.
// grid = 264 (original gate rows), block = 68.
// ---------------------------------------------------------------------------
__global__ void precompute_kernel(const float* __restrict__ Wih,
                                  const float* __restrict__ Whh,
                                  const float* __restrict__ bih,
                                  const float* __restrict__ bhh,
                                  const float* __restrict__ fcW,
                                  const float* __restrict__ fcb,
                                  const float* __restrict__ emb) {
    const int j = blockIdx.x;            // original row: gate*66 + unit
    const int gate = j / DEC_H;
    const int unit = j % DEC_H;
    const int r = unit * 4 + gate;       // permuted row
    const int d = threadIdx.x;

    if (d < DEC_H) {
        float s0 = 0.f, s1 = 0.f, s2 = 0.f, s3 = 0.f;
#pragma unroll
        for (int e = 0; e < EMBED; e += 4) {
            s0 = fmaf(Wih[j * EMBED + e + 0], fcW[(e + 0) * DEC_H + d], s0);
            s1 = fmaf(Wih[j * EMBED + e + 1], fcW[(e + 1) * DEC_H + d], s1);
            s2 = fmaf(Wih[j * EMBED + e + 2], fcW[(e + 2) * DEC_H + d], s2);
            s3 = fmaf(Wih[j * EMBED + e + 3], fcW[(e + 3) * DEC_H + d], s3);
        }
        g_Wc[r * HPAD + d] = ((s0 + s1) + (s2 + s3)) + Whh[j * DEC_H + d];
    } else if (d == DEC_H) {             // bias (folded fc_b path)
        g_Wc[r * HPAD + d] = 0.0f;       // padding col
        float s0 = 0.f, s1 = 0.f, s2 = 0.f, s3 = 0.f;
#pragma unroll
        for (int e = 0; e < EMBED; e += 4) {
            float w0 = Wih[j * EMBED + e + 0], w1 = Wih[j * EMBED + e + 1];
            float w2 = Wih[j * EMBED + e + 2], w3 = Wih[j * EMBED + e + 3];
            s0 = fmaf(w0, fcb[e + 0], s0);
            s1 = fmaf(w1, fcb[e + 1], s1);
            s2 = fmaf(w2, fcb[e + 2], s2);
            s3 = fmaf(w3, fcb[e + 3], s3);
        }
        g_bias[r] = ((s0 + s1) + (s2 + s3)) + bih[j] + bhh[j];
    } else if (d == DEC_H + 1) {         // first-step gates (emb[0] path)
        g_Wc[r * HPAD + d] = 0.0f;       // padding col
        float s0 = 0.f, s1 = 0.f, s2 = 0.f, s3 = 0.f;
#pragma unroll
        for (int e = 0; e < EMBED; e += 4) {
            s0 = fmaf(Wih[j * EMBED + e + 0], emb[e + 0], s0);
            s1 = fmaf(Wih[j * EMBED + e + 1], emb[e + 1], s1);
            s2 = fmaf(Wih[j * EMBED + e + 2], emb[e + 2], s2);
            s3 = fmaf(Wih[j * EMBED + e + 3], emb[e + 3], s3);
        }
        g_gx0[r] = ((s0 + s1) + (s2 + s3)) + bih[j] + bhh[j];
    }
}

// ---------------------------------------------------------------------------
// Kernel 2: sequential recurrence, single CTA, 264 threads.
// Lane 4u+g owns gate g of unit u. One __syncthreads per step; h ping-pong.
// ---------------------------------------------------------------------------
__global__ __launch_bounds__(264, 1) void recur_kernel(int T) {
    __shared__ __align__(16) float hsm[2][HPAD];
    const int tid  = threadIdx.x;
    const int gate = tid & 3;
    const int unit = tid >> 2;
    const unsigned mask = (tid >= 256) ? 0x000000FFu : 0xFFFFFFFFu;

    ulonglong2 w[17];
    const ulonglong2* ws = reinterpret_cast<const ulonglong2*>(g_Wc) + tid * 17;
#pragma unroll
    for (int k = 0; k < 17; k++) w[k] = ws[k];
    float bcur = g_gx0[tid];         // step-0 "bias" = full first-step gates
    const float bias = g_bias[tid];

    if (tid < 2 * HPAD) reinterpret_cast<float*>(hsm)[tid] = 0.0f;
    float cst = 0.0f;                // cell state, lives in gate-0 lanes
    __syncthreads();

    for (int t = 0; t < T; t++) {
        const ulonglong2* h2 = reinterpret_cast<const ulonglong2*>(hsm[t & 1]);
        ull a0 = 0ull, a1 = 0ull, a2 = 0ull, a3 = 0ull;
#pragma unroll
        for (int k = 0; k < 17; k++) {
            ulonglong2 hv = h2[k];               // broadcast LDS.128
            if (k & 1) { fma2(a2, w[k].x, hv.x); fma2(a3, w[k].y, hv.y); }
            else       { fma2(a0, w[k].x, hv.x); fma2(a1, w[k].y, hv.y); }
        }
        add2(a0, a2); add2(a1, a3); add2(a0, a1);
        float2 s = up2(a0);
        float g = (bcur + s.x) + s.y;
        bcur = bias;

        float a = (gate == 2) ? fast_tanh(g) : fast_sigmoid(g);

        // gate-0 lane gathers f,g,o from lanes +1,+2,+3 of its quad
        float fv = __shfl_down_sync(mask, a, 1, 4);
        float gv = __shfl_down_sync(mask, a, 2, 4);
        float ov = __shfl_down_sync(mask, a, 3, 4);

        if (gate == 0) {
            cst = fmaf(fv, cst, a * gv);
            float h = ov * fast_tanh(cst);
            hsm[(t + 1) & 1][unit] = h;          // write to the OTHER buffer
            g_hist[t * DEC_H + unit] = h;
        }
        __syncthreads();
    }
}

// ---------------------------------------------------------------------------
// Kernel 3: broadcast [T*66] trajectory to all B rows. float4 copies.
// ---------------------------------------------------------------------------
__global__ void bcast_kernel(float* __restrict__ out, int rowlen4) {
    int i = blockIdx.x * blockDim.x + threadIdx.x;
    int b = blockIdx.y;
    if (i < rowlen4) {
        reinterpret_cast<float4*>(out)[(size_t)b * rowlen4 + i] =
            reinterpret_cast<const float4*>(g_hist)[i];
    }
}

// ---------------------------------------------------------------------------
// Inputs: 0:x 1:c 2:emb 3..6:enc_* 7:dec_W_ih 8:dec_W_hh 9:dec_b_ih
// 10:dec_b_hh 11:fc_W 12:fc_b. Encoder is dead code w.r.t. the output.
// ---------------------------------------------------------------------------
extern "C" void kernel_launch(void* const* d_in, const int* in_sizes, int n_in,
                              void* d_out, int out_size) {
    const float* emb = (const float*)d_in[2];
    const float* Wih = (const float*)d_in[7];
    const float* Whh = (const float*)d_in[8];
    const float* bih = (const float*)d_in[9];
    const float* bhh = (const float*)d_in[10];
    const float* fcW = (const float*)d_in[11];
    const float* fcb = (const float*)d_in[12];

    const int B = 128;
    int T = out_size / (B * DEC_H);
    if (T > MAXT) T = MAXT;

    precompute_kernel<<<G4, HPAD>>>(Wih, Whh, bih, bhh, fcW, fcb, emb);
    recur_kernel<<<1, 264>>>(T);

    int rowlen4 = (T * DEC_H) / 4;
    dim3 grid((rowlen4 + 255) / 256, B);
    bcast_kernel<<<grid, 256>>>((float*)d_out, rowlen4);
}